// round 2
// baseline (speedup 1.0000x reference)
#include <cuda_runtime.h>
#include <math.h>

#define NB 16
#define NC 256
#define NE 9216
#define NE4 (NE / 4)
#define KSEL 4096

// Scratch (no allocations allowed) — device globals, 16B-aligned via vector types.
__device__ float4 g_score4[NB * NE4];   // scores, viewed as float[NB*NE]
__device__ int4   g_pos4[NB * NE4];     // pos[e] = output slot if kept, -1 if dropped

// ---------------------------------------------------------------------------
// Kernel 1: score[b,e] = sum_c x[b,c,e]^2   (vectorized over e, float4)
// grid = (NE4/256, NB) = (9, 16), block = 256.
// ---------------------------------------------------------------------------
__global__ void score_kernel(const float4* __restrict__ x4) {
    int e4 = blockIdx.x * blockDim.x + threadIdx.x;
    int b  = blockIdx.y;
    const float4* p = x4 + (size_t)b * NC * NE4 + e4;
    float ax = 0.f, ay = 0.f, az = 0.f, aw = 0.f;
#pragma unroll 8
    for (int c = 0; c < NC; ++c) {
        float4 v = __ldg(p + (size_t)c * NE4);
        ax = fmaf(v.x, v.x, ax);
        ay = fmaf(v.y, v.y, ay);
        az = fmaf(v.z, v.z, az);
        aw = fmaf(v.w, v.w, aw);
    }
    g_score4[b * NE4 + e4] = make_float4(ax, ay, az, aw);
}

// ---------------------------------------------------------------------------
// Block exclusive scan over 1024 threads (32 warps). wsum is shared[32].
// ---------------------------------------------------------------------------
__device__ __forceinline__ int block_exscan(int val, int t, int* wsum) {
    int lane = t & 31, w = t >> 5;
    int x = val;
#pragma unroll
    for (int d = 1; d < 32; d <<= 1) {
        int y = __shfl_up_sync(0xFFFFFFFFu, x, d);
        if (lane >= d) x += y;
    }
    __syncthreads();               // protect wsum reuse across calls
    if (lane == 31) wsum[w] = x;   // inclusive warp total
    __syncthreads();
    if (w == 0) {
        int s = wsum[lane];
        int xs = s;
#pragma unroll
        for (int d = 1; d < 32; d <<= 1) {
            int y = __shfl_up_sync(0xFFFFFFFFu, xs, d);
            if (lane >= d) xs += y;
        }
        wsum[lane] = xs - s;       // exclusive warp offsets
    }
    __syncthreads();
    return wsum[w] + x - val;      // exclusive for this thread
}

// ---------------------------------------------------------------------------
// Kernel 2: per-mesh K-th-largest threshold (MSD radix select, 4x8-bit) +
// stable tie-break by ascending index + forward position map.
// One CTA of 1024 threads per mesh.
// ---------------------------------------------------------------------------
__global__ __launch_bounds__(1024) void select_kernel(const void* __restrict__ ec_raw) {
    __shared__ unsigned int skey[NE];      // 36 KB
    __shared__ unsigned int hist[256];
    __shared__ unsigned int suf[256];
    __shared__ unsigned int bcast[2];
    __shared__ int wsum[32];

    const int t = threadIdx.x;
    const int b = blockIdx.x;

    // edges_count dtype robustness: int64 vs int32 (jax x64 demotion).
    // Counts are always >= 8704, never 0, so ec32[1]==0 <=> int64 layout.
    const int* ec32 = (const int*)ec_raw;
    long long cnt;
    if (ec32[1] == 0) cnt = ((const long long*)ec_raw)[b];
    else              cnt = (long long)ec32[b];

    // Load order-transformed keys (monotone float->uint; invalid edges -> 0,
    // below any valid non-negative score which maps to >= 0x80000000).
    const float* score = (const float*)g_score4;
    for (int e = t; e < NE; e += 1024) {
        unsigned int bits = 0u;
        if (e < cnt) {
            bits = __float_as_uint(score[b * NE + e]);
            bits = (bits & 0x80000000u) ? ~bits : (bits | 0x80000000u);
        }
        skey[e] = bits;
    }
    __syncthreads();

    // 4-pass MSD radix select for the KSEL-th largest key.
    unsigned int prefix = 0, pmask = 0;
    int kth = KSEL;
    for (int shift = 24; shift >= 0; shift -= 8) {
        if (t < 256) hist[t] = 0;
        __syncthreads();
        for (int e = t; e < NE; e += 1024) {
            unsigned int key = skey[e];
            if ((key & pmask) == prefix)
                atomicAdd(&hist[(key >> shift) & 255u], 1u);
        }
        __syncthreads();
        // Parallel inclusive suffix scan of hist into suf (256 threads).
        if (t < 256) suf[t] = hist[t];
        __syncthreads();
#pragma unroll
        for (int d = 1; d < 256; d <<= 1) {
            unsigned int v = 0;
            if (t < 256) v = suf[t] + ((t + d < 256) ? suf[t + d] : 0u);
            __syncthreads();
            if (t < 256) suf[t] = v;
            __syncthreads();
        }
        // Find largest bin v with S(v) >= kth; exactly one thread matches.
        if (t < 256) {
            int Sv = (int)suf[t];
            int Sn = (t == 255) ? 0 : (int)suf[t + 1];
            if (Sv >= kth && Sn < kth) {
                bcast[0] = (unsigned int)t;
                bcast[1] = (unsigned int)(kth - Sn);
            }
        }
        __syncthreads();
        prefix |= bcast[0] << shift;
        pmask  |= 0xFFu << shift;
        kth = (int)bcast[1];
        __syncthreads();
    }

    const unsigned int T = prefix;   // key of the KSEL-th largest element
    const int needed_eq = kth;       // # of ==T elements to keep (lowest idx first)

    // Per-thread contiguous chunk of 9 elements (1024 * 9 = 9216).
    const int base = t * 9;
    unsigned int keys[9];
#pragma unroll
    for (int i = 0; i < 9; ++i) keys[i] = skey[base + i];

    // Pass A: rank among ==T elements (index order).
    int eqpre[9]; int eqcnt = 0;
#pragma unroll
    for (int i = 0; i < 9; ++i) { eqpre[i] = eqcnt; eqcnt += (keys[i] == T); }
    int eqoff = block_exscan(eqcnt, t, wsum);

    // Pass B: keep-flag compaction -> forward position map.
    int kpre[9]; int kcnt = 0;
#pragma unroll
    for (int i = 0; i < 9; ++i) {
        bool keep = (keys[i] > T) || (keys[i] == T && (eqoff + eqpre[i]) < needed_eq);
        kpre[i] = kcnt; kcnt += keep;
    }
    int koff = block_exscan(kcnt, t, wsum);
    int* pos = (int*)g_pos4;
#pragma unroll
    for (int i = 0; i < 9; ++i) {
        bool keep = (keys[i] > T) || (keys[i] == T && (eqoff + eqpre[i]) < needed_eq);
        pos[b * NE + base + i] = keep ? (koff + kpre[i]) : -1;
    }
}

// ---------------------------------------------------------------------------
// Kernel 3: forward scatter — fully coalesced float4 reads of x; kept
// elements written to their dense ascending output slots (L2 merges the
// predicated STG.32s into full dirty sectors).
// grid = (NE4/256, NC/8, NB), block = 256. pos reused across 8 channels.
// ---------------------------------------------------------------------------
__global__ void scatter_kernel(const float4* __restrict__ x4,
                               float* __restrict__ out) {
    int e4 = blockIdx.x * blockDim.x + threadIdx.x;  // 0..NE4-1
    int c0 = blockIdx.y * 8;
    int b  = blockIdx.z;

    int4 pos = g_pos4[b * NE4 + e4];
    const float4* xp = x4 + ((size_t)b * NC + c0) * NE4 + e4;
    float* op = out + ((size_t)b * NC + c0) * KSEL;

#pragma unroll
    for (int j = 0; j < 8; ++j) {
        float4 v = __ldg(xp + (size_t)j * NE4);
        float* o = op + (size_t)j * KSEL;
        if (pos.x >= 0) o[pos.x] = v.x;
        if (pos.y >= 0) o[pos.y] = v.y;
        if (pos.z >= 0) o[pos.z] = v.z;
        if (pos.w >= 0) o[pos.w] = v.w;
    }
}

// ---------------------------------------------------------------------------
extern "C" void kernel_launch(void* const* d_in, const int* in_sizes, int n_in,
                              void* d_out, int out_size) {
    const float4* x4 = (const float4*)d_in[0];
    const void* ec = d_in[1];     // edges_count (int64 or int32; detected on device)
    float* out = (float*)d_out;

    dim3 g1(NE4 / 256, NB);
    score_kernel<<<g1, 256>>>(x4);
    select_kernel<<<NB, 1024>>>(ec);
    dim3 g3(NE4 / 256, NC / 8, NB);
    scatter_kernel<<<g3, 256>>>(x4, out);
}

// round 3
// speedup vs baseline: 1.0221x; 1.0221x over previous
#include <cuda_runtime.h>
#include <math.h>

#define NB 16
#define NC 256
#define NE 9216
#define NE4 (NE / 4)
#define KSEL 4096

// Scratch (no allocations allowed) — device globals, 16B-aligned via vector types.
__device__ float4 g_score4[NB * NE4];   // scores, viewed as float[NB*NE]
__device__ int4   g_pos4[NB * NE4];     // pos[e] = output slot if kept, -1 if dropped

// ---------------------------------------------------------------------------
// Kernel 1: score[b,e] = sum_c x[b,c,e]^2   (float4 over e, channel-split x4)
// grid = (NE4/64, NB) = (36, 16) = 576 CTAs, block = 256.
// tid = 64 e4-lanes x 4 channel-groups of 64 channels; SMEM reduce at end.
// ---------------------------------------------------------------------------
__global__ __launch_bounds__(256) void score_kernel(const float4* __restrict__ x4) {
    __shared__ float4 part[4][64];
    const int tid = threadIdx.x;
    const int el  = tid & 63;          // e4 lane within block
    const int cg  = tid >> 6;          // channel group 0..3
    const int e4  = blockIdx.x * 64 + el;
    const int b   = blockIdx.y;

    const float4* p = x4 + ((size_t)b * NC + (size_t)cg * 64) * NE4 + e4;
    float ax = 0.f, ay = 0.f, az = 0.f, aw = 0.f;
#pragma unroll 8
    for (int c = 0; c < 64; ++c) {
        float4 v = __ldg(p + (size_t)c * NE4);
        ax = fmaf(v.x, v.x, ax);
        ay = fmaf(v.y, v.y, ay);
        az = fmaf(v.z, v.z, az);
        aw = fmaf(v.w, v.w, aw);
    }
    part[cg][el] = make_float4(ax, ay, az, aw);
    __syncthreads();
    if (tid < 64) {
        float4 a = part[0][tid], b2 = part[1][tid],
               c2 = part[2][tid], d = part[3][tid];
        g_score4[b * NE4 + blockIdx.x * 64 + tid] =
            make_float4(a.x + b2.x + c2.x + d.x,
                        a.y + b2.y + c2.y + d.y,
                        a.z + b2.z + c2.z + d.z,
                        a.w + b2.w + c2.w + d.w);
    }
}

// ---------------------------------------------------------------------------
// Block exclusive scan over 1024 threads (32 warps). wsum is shared[32].
// ---------------------------------------------------------------------------
__device__ __forceinline__ int block_exscan(int val, int t, int* wsum) {
    int lane = t & 31, w = t >> 5;
    int x = val;
#pragma unroll
    for (int d = 1; d < 32; d <<= 1) {
        int y = __shfl_up_sync(0xFFFFFFFFu, x, d);
        if (lane >= d) x += y;
    }
    __syncthreads();               // protect wsum reuse across calls
    if (lane == 31) wsum[w] = x;   // inclusive warp total
    __syncthreads();
    if (w == 0) {
        int s = wsum[lane];
        int xs = s;
#pragma unroll
        for (int d = 1; d < 32; d <<= 1) {
            int y = __shfl_up_sync(0xFFFFFFFFu, xs, d);
            if (lane >= d) xs += y;
        }
        wsum[lane] = xs - s;       // exclusive warp offsets
    }
    __syncthreads();
    return wsum[w] + x - val;      // exclusive for this thread
}

// ---------------------------------------------------------------------------
// Kernel 2: per-mesh K-th-largest threshold (MSD radix select, 4x8-bit) +
// stable tie-break by ascending index + forward position map.
// One CTA of 1024 threads per mesh.
// ---------------------------------------------------------------------------
__global__ __launch_bounds__(1024) void select_kernel(const void* __restrict__ ec_raw) {
    __shared__ unsigned int skey[NE];      // 36 KB
    __shared__ unsigned int hist[256];
    __shared__ unsigned int suf[256];
    __shared__ unsigned int bcast[2];
    __shared__ int wsum[32];

    const int t = threadIdx.x;
    const int b = blockIdx.x;

    // edges_count dtype robustness: int64 vs int32 (jax x64 demotion).
    // Counts are always >= 8704, never 0, so ec32[1]==0 <=> int64 layout.
    const int* ec32 = (const int*)ec_raw;
    long long cnt;
    if (ec32[1] == 0) cnt = ((const long long*)ec_raw)[b];
    else              cnt = (long long)ec32[b];

    // Load order-transformed keys (monotone float->uint; invalid edges -> 0,
    // below any valid non-negative score which maps to >= 0x80000000).
    const float* score = (const float*)g_score4;
    for (int e = t; e < NE; e += 1024) {
        unsigned int bits = 0u;
        if (e < cnt) {
            bits = __float_as_uint(score[b * NE + e]);
            bits = (bits & 0x80000000u) ? ~bits : (bits | 0x80000000u);
        }
        skey[e] = bits;
    }
    __syncthreads();

    // 4-pass MSD radix select for the KSEL-th largest key.
    unsigned int prefix = 0, pmask = 0;
    int kth = KSEL;
    for (int shift = 24; shift >= 0; shift -= 8) {
        if (t < 256) hist[t] = 0;
        __syncthreads();
        for (int e = t; e < NE; e += 1024) {
            unsigned int key = skey[e];
            if ((key & pmask) == prefix)
                atomicAdd(&hist[(key >> shift) & 255u], 1u);
        }
        __syncthreads();
        // Parallel inclusive suffix scan of hist into suf (256 threads).
        if (t < 256) suf[t] = hist[t];
        __syncthreads();
#pragma unroll
        for (int d = 1; d < 256; d <<= 1) {
            unsigned int v = 0;
            if (t < 256) v = suf[t] + ((t + d < 256) ? suf[t + d] : 0u);
            __syncthreads();
            if (t < 256) suf[t] = v;
            __syncthreads();
        }
        // Find largest bin v with S(v) >= kth; exactly one thread matches.
        if (t < 256) {
            int Sv = (int)suf[t];
            int Sn = (t == 255) ? 0 : (int)suf[t + 1];
            if (Sv >= kth && Sn < kth) {
                bcast[0] = (unsigned int)t;
                bcast[1] = (unsigned int)(kth - Sn);
            }
        }
        __syncthreads();
        prefix |= bcast[0] << shift;
        pmask  |= 0xFFu << shift;
        kth = (int)bcast[1];
        __syncthreads();
    }

    const unsigned int T = prefix;   // key of the KSEL-th largest element
    const int needed_eq = kth;       // # of ==T elements to keep (lowest idx first)

    // Per-thread contiguous chunk of 9 elements (1024 * 9 = 9216).
    const int base = t * 9;
    unsigned int keys[9];
#pragma unroll
    for (int i = 0; i < 9; ++i) keys[i] = skey[base + i];

    // Pass A: rank among ==T elements (index order).
    int eqpre[9]; int eqcnt = 0;
#pragma unroll
    for (int i = 0; i < 9; ++i) { eqpre[i] = eqcnt; eqcnt += (keys[i] == T); }
    int eqoff = block_exscan(eqcnt, t, wsum);

    // Pass B: keep-flag compaction -> forward position map.
    int kpre[9]; int kcnt = 0;
#pragma unroll
    for (int i = 0; i < 9; ++i) {
        bool keep = (keys[i] > T) || (keys[i] == T && (eqoff + eqpre[i]) < needed_eq);
        kpre[i] = kcnt; kcnt += keep;
    }
    int koff = block_exscan(kcnt, t, wsum);
    int* pos = (int*)g_pos4;
#pragma unroll
    for (int i = 0; i < 9; ++i) {
        bool keep = (keys[i] > T) || (keys[i] == T && (eqoff + eqpre[i]) < needed_eq);
        pos[b * NE + base + i] = keep ? (koff + kpre[i]) : -1;
    }
}

// ---------------------------------------------------------------------------
// Kernel 3: forward scatter — fully coalesced float4 reads of x; kept
// elements written to their dense ascending output slots (L2 merges the
// predicated STG.32s into full dirty sectors).
// grid = (NE4/256, NC/8, NB), block = 256. pos reused across 8 channels.
// ---------------------------------------------------------------------------
__global__ void scatter_kernel(const float4* __restrict__ x4,
                               float* __restrict__ out) {
    int e4 = blockIdx.x * blockDim.x + threadIdx.x;  // 0..NE4-1
    int c0 = blockIdx.y * 8;
    int b  = blockIdx.z;

    int4 pos = g_pos4[b * NE4 + e4];
    const float4* xp = x4 + ((size_t)b * NC + c0) * NE4 + e4;
    float* op = out + ((size_t)b * NC + c0) * KSEL;

#pragma unroll
    for (int j = 0; j < 8; ++j) {
        float4 v = __ldg(xp + (size_t)j * NE4);
        float* o = op + (size_t)j * KSEL;
        if (pos.x >= 0) o[pos.x] = v.x;
        if (pos.y >= 0) o[pos.y] = v.y;
        if (pos.z >= 0) o[pos.z] = v.z;
        if (pos.w >= 0) o[pos.w] = v.w;
    }
}

// ---------------------------------------------------------------------------
extern "C" void kernel_launch(void* const* d_in, const int* in_sizes, int n_in,
                              void* d_out, int out_size) {
    const float4* x4 = (const float4*)d_in[0];
    const void* ec = d_in[1];     // edges_count (int64 or int32; detected on device)
    float* out = (float*)d_out;

    dim3 g1(NE4 / 64, NB);
    score_kernel<<<g1, 256>>>(x4);
    select_kernel<<<NB, 1024>>>(ec);
    dim3 g3(NE4 / 256, NC / 8, NB);
    scatter_kernel<<<g3, 256>>>(x4, out);
}

// round 4
// speedup vs baseline: 1.1535x; 1.1286x over previous
#include <cuda_runtime.h>
#include <math.h>

#define NB 16
#define NC 256
#define NE 9216
#define NE4 (NE / 4)
#define KSEL 4096

// Scratch (no allocations allowed) — device globals, 16B-aligned via vector types.
__device__ float4 g_score4[NB * NE4];   // scores, viewed as float[NB*NE]
__device__ int4   g_pos4[NB * NE4];     // pos[e] = output slot if kept, -1 if dropped

// ---------------------------------------------------------------------------
// Kernel 1: score[b,e] = sum_c x[b,c,e]^2   (float4 over e, channel-split x8)
// grid = (NE4/32, NB) = (72, 16) = 1152 CTAs, block = 256.
// block = 32 e4-lanes x 8 channel-groups of 32 channels; SMEM reduce at end.
// ---------------------------------------------------------------------------
__global__ __launch_bounds__(256) void score_kernel(const float4* __restrict__ x4) {
    __shared__ float4 part[8][32];
    const int tid = threadIdx.x;
    const int el  = tid & 31;          // e4 lane within block
    const int cg  = tid >> 5;          // channel group 0..7
    const int e4  = blockIdx.x * 32 + el;
    const int b   = blockIdx.y;

    const float4* p = x4 + ((size_t)b * NC + (size_t)cg * 32) * NE4 + e4;
    float ax = 0.f, ay = 0.f, az = 0.f, aw = 0.f;
#pragma unroll 8
    for (int c = 0; c < 32; ++c) {
        float4 v = __ldg(p + (size_t)c * NE4);
        ax = fmaf(v.x, v.x, ax);
        ay = fmaf(v.y, v.y, ay);
        az = fmaf(v.z, v.z, az);
        aw = fmaf(v.w, v.w, aw);
    }
    part[cg][el] = make_float4(ax, ay, az, aw);
    __syncthreads();
    if (tid < 32) {
        float4 s = part[0][tid];
#pragma unroll
        for (int g = 1; g < 8; ++g) {
            float4 q = part[g][tid];
            s.x += q.x; s.y += q.y; s.z += q.z; s.w += q.w;
        }
        g_score4[b * NE4 + blockIdx.x * 32 + tid] = s;
    }
}

// ---------------------------------------------------------------------------
// Block exclusive scan over 1024 threads (32 warps). wsum is shared[32].
// ---------------------------------------------------------------------------
__device__ __forceinline__ int block_exscan(int val, int t, int* wsum) {
    int lane = t & 31, w = t >> 5;
    int x = val;
#pragma unroll
    for (int d = 1; d < 32; d <<= 1) {
        int y = __shfl_up_sync(0xFFFFFFFFu, x, d);
        if (lane >= d) x += y;
    }
    __syncthreads();               // protect wsum reuse across calls
    if (lane == 31) wsum[w] = x;   // inclusive warp total
    __syncthreads();
    if (w == 0) {
        int s = wsum[lane];
        int xs = s;
#pragma unroll
        for (int d = 1; d < 32; d <<= 1) {
            int y = __shfl_up_sync(0xFFFFFFFFu, xs, d);
            if (lane >= d) xs += y;
        }
        wsum[lane] = xs - s;       // exclusive warp offsets
    }
    __syncthreads();
    return wsum[w] + x - val;      // exclusive for this thread
}

// ---------------------------------------------------------------------------
// Kernel 2: per-mesh K-th-largest threshold (MSD radix select, 4x8-bit,
// warp-aggregated histogram atomics) + stable tie-break by ascending index
// + forward position map. One CTA of 1024 threads per mesh.
// ---------------------------------------------------------------------------
__global__ __launch_bounds__(1024) void select_kernel(const void* __restrict__ ec_raw) {
    __shared__ unsigned int skey[NE];      // 36 KB
    __shared__ unsigned int hist[256];
    __shared__ unsigned int suf[256];
    __shared__ unsigned int bcast[2];
    __shared__ int wsum[32];

    const int t = threadIdx.x;
    const int b = blockIdx.x;

    // edges_count dtype robustness: int64 vs int32 (jax x64 demotion).
    // Counts are always >= 8704, never 0, so ec32[1]==0 <=> int64 layout.
    const int* ec32 = (const int*)ec_raw;
    long long cnt;
    if (ec32[1] == 0) cnt = ((const long long*)ec_raw)[b];
    else              cnt = (long long)ec32[b];

    // Load order-transformed keys (monotone float->uint; invalid edges -> 0,
    // below any valid non-negative score which maps to >= 0x80000000).
    const float* score = (const float*)g_score4;
    for (int e = t; e < NE; e += 1024) {
        unsigned int bits = 0u;
        if (e < cnt) {
            bits = __float_as_uint(score[b * NE + e]);
            bits = (bits & 0x80000000u) ? ~bits : (bits | 0x80000000u);
        }
        skey[e] = bits;
    }
    __syncthreads();

    // 4-pass MSD radix select for the KSEL-th largest key.
    // Scores cluster tightly (chi^2_256), so early digits are nearly
    // constant: aggregate same-digit atomics per warp via match_any.
    unsigned int prefix = 0, pmask = 0;
    int kth = KSEL;
    for (int shift = 24; shift >= 0; shift -= 8) {
        if (t < 256) hist[t] = 0;
        __syncthreads();
#pragma unroll
        for (int e = t; e < NE; e += 1024) {   // exactly 9 uniform iterations
            unsigned int key = skey[e];
            bool ok = ((key & pmask) == prefix);
            unsigned int digit = (key >> shift) & 255u;
            unsigned int active = __ballot_sync(0xFFFFFFFFu, ok);
            if (ok) {
                unsigned int peers = __match_any_sync(active, digit);
                if ((t & 31) == __ffs(peers) - 1)
                    atomicAdd(&hist[digit], (unsigned int)__popc(peers));
            }
        }
        __syncthreads();
        // Parallel inclusive suffix scan of hist into suf (256 threads).
        if (t < 256) suf[t] = hist[t];
        __syncthreads();
#pragma unroll
        for (int d = 1; d < 256; d <<= 1) {
            unsigned int v = 0;
            if (t < 256) v = suf[t] + ((t + d < 256) ? suf[t + d] : 0u);
            __syncthreads();
            if (t < 256) suf[t] = v;
            __syncthreads();
        }
        // Find largest bin v with S(v) >= kth; exactly one thread matches.
        if (t < 256) {
            int Sv = (int)suf[t];
            int Sn = (t == 255) ? 0 : (int)suf[t + 1];
            if (Sv >= kth && Sn < kth) {
                bcast[0] = (unsigned int)t;
                bcast[1] = (unsigned int)(kth - Sn);
            }
        }
        __syncthreads();
        prefix |= bcast[0] << shift;
        pmask  |= 0xFFu << shift;
        kth = (int)bcast[1];
        __syncthreads();
    }

    const unsigned int T = prefix;   // key of the KSEL-th largest element
    const int needed_eq = kth;       // # of ==T elements to keep (lowest idx first)

    // Per-thread contiguous chunk of 9 elements (1024 * 9 = 9216).
    const int base = t * 9;
    unsigned int keys[9];
#pragma unroll
    for (int i = 0; i < 9; ++i) keys[i] = skey[base + i];

    // Pass A: rank among ==T elements (index order).
    int eqpre[9]; int eqcnt = 0;
#pragma unroll
    for (int i = 0; i < 9; ++i) { eqpre[i] = eqcnt; eqcnt += (keys[i] == T); }
    int eqoff = block_exscan(eqcnt, t, wsum);

    // Pass B: keep-flag compaction -> forward position map.
    int kpre[9]; int kcnt = 0;
#pragma unroll
    for (int i = 0; i < 9; ++i) {
        bool keep = (keys[i] > T) || (keys[i] == T && (eqoff + eqpre[i]) < needed_eq);
        kpre[i] = kcnt; kcnt += keep;
    }
    int koff = block_exscan(kcnt, t, wsum);
    int* pos = (int*)g_pos4;
#pragma unroll
    for (int i = 0; i < 9; ++i) {
        bool keep = (keys[i] > T) || (keys[i] == T && (eqoff + eqpre[i]) < needed_eq);
        pos[b * NE + base + i] = keep ? (koff + kpre[i]) : -1;
    }
}

// ---------------------------------------------------------------------------
// Kernel 3: forward scatter — fully coalesced float4 reads of x; kept
// elements written to their dense ascending output slots (L2 merges the
// predicated STG.32s into full dirty sectors).
// grid = (NE4/256, NC/8, NB), block = 256. pos reused across 8 channels.
// ---------------------------------------------------------------------------
__global__ void scatter_kernel(const float4* __restrict__ x4,
                               float* __restrict__ out) {
    int e4 = blockIdx.x * blockDim.x + threadIdx.x;  // 0..NE4-1
    int c0 = blockIdx.y * 8;
    int b  = blockIdx.z;

    int4 pos = g_pos4[b * NE4 + e4];
    const float4* xp = x4 + ((size_t)b * NC + c0) * NE4 + e4;
    float* op = out + ((size_t)b * NC + c0) * KSEL;

#pragma unroll
    for (int j = 0; j < 8; ++j) {
        float4 v = __ldg(xp + (size_t)j * NE4);
        float* o = op + (size_t)j * KSEL;
        if (pos.x >= 0) o[pos.x] = v.x;
        if (pos.y >= 0) o[pos.y] = v.y;
        if (pos.z >= 0) o[pos.z] = v.z;
        if (pos.w >= 0) o[pos.w] = v.w;
    }
}

// ---------------------------------------------------------------------------
extern "C" void kernel_launch(void* const* d_in, const int* in_sizes, int n_in,
                              void* d_out, int out_size) {
    const float4* x4 = (const float4*)d_in[0];
    const void* ec = d_in[1];     // edges_count (int64 or int32; detected on device)
    float* out = (float*)d_out;

    dim3 g1(NE4 / 32, NB);
    score_kernel<<<g1, 256>>>(x4);
    select_kernel<<<NB, 1024>>>(ec);
    dim3 g3(NE4 / 256, NC / 8, NB);
    scatter_kernel<<<g3, 256>>>(x4, out);
}